// round 13
// baseline (speedup 1.0000x reference)
#include <cuda_runtime.h>
#include <cstdint>
#include <math.h>

// NaiveFourierKANLayer, warp-specialized fp16 MMA, 64x64 warp tiles:
//   y[32768,256] = A[32768,4096] @ W[4096,256] + bias
// CTA = 128 rows x ALL 256 outputs, 320 threads:
//   warps 0-7 consumers, (2,4) grid of 64x64 tiles -> 8 LDSM.x4 per 32 MMAs
//   warps 8-9 producers (A-gen 4 rows/thread + 64KB W cp.async per stage)
// Stage = 2 input dims (128 k). 2 stages. SMEM 192KB, 1 CTA/SM.

#define NROWS   32768
#define INDIM   64
#define OUTDIM  256

// ---------- helpers ----------
__device__ __forceinline__ uint32_t smem_u32(const void* p) {
    uint32_t a;
    asm("{ .reg .u64 t; cvta.to.shared.u64 t, %1; cvt.u32.u64 %0, t; }" : "=r"(a) : "l"(p));
    return a;
}
__device__ __forceinline__ uint32_t pack_f16(float e0, float e1) {   // low half = e0
    uint32_t r;
    asm("cvt.rn.f16x2.f32 %0, %1, %2;" : "=r"(r) : "f"(e1), "f"(e0));
    return r;
}
__device__ __forceinline__ uint32_t swz(uint32_t off) { return off ^ ((off >> 3) & 0x70); }

__device__ __forceinline__ void cpa16(uint32_t dst, const void* src) {
    asm volatile("cp.async.cg.shared.global [%0], [%1], 16;" :: "r"(dst), "l"(src) : "memory");
}
#define CP_COMMIT() asm volatile("cp.async.commit_group;" ::: "memory")
#define CP_WAIT0()  asm volatile("cp.async.wait_group 0;" ::: "memory")

// named split barriers, whole-CTA count (320)
#define BAR_SYNC(id)   asm volatile("bar.sync %0, 320;"   :: "r"(id) : "memory")
#define BAR_ARRIVE(id) asm volatile("bar.arrive %0, 320;" :: "r"(id) : "memory")
// FULL[s] = 1+s (producers arrive, consumers sync)
// EMPTY[s] = 3+s (consumers arrive, producers sync)

__device__ __forceinline__ void ldsm4(uint32_t* r, uint32_t addr) {
    asm volatile("ldmatrix.sync.aligned.m8n8.x4.shared.b16 {%0,%1,%2,%3}, [%4];"
                 : "=r"(r[0]), "=r"(r[1]), "=r"(r[2]), "=r"(r[3]) : "r"(addr));
}
__device__ __forceinline__ void mma_f16(float* d, const uint32_t* a, uint32_t b0, uint32_t b1) {
    asm volatile("mma.sync.aligned.m16n8k16.row.col.f32.f16.f16.f32 "
                 "{%0,%1,%2,%3},{%4,%5,%6,%7},{%8,%9},{%0,%1,%2,%3};"
                 : "+f"(d[0]), "+f"(d[1]), "+f"(d[2]), "+f"(d[3])
                 : "r"(a[0]), "r"(a[1]), "r"(a[2]), "r"(a[3]), "r"(b0), "r"(b1));
}

// ---------- pre-swizzled fp16 W tiles ----------
// g_wt[i] = 32KB tile: 256 rows (o), 128 bytes each; byte (o,c) at swz(o*128+c)
// c = f*2, f in [0,64): f<32 -> cos k=f+1 ; f>=32 -> sin k=f-31
__device__ __align__(1024) unsigned char g_wt[64 * 32768];

__global__ void kan_wprep(const float* __restrict__ w) {
    const int i = blockIdx.x;
    const int o = threadIdx.x;           // 0..255
    const float* pc = w + ((size_t)(0 * 256 + o) * 64 + i) * 32;
    const float* ps = w + ((size_t)(1 * 256 + o) * 64 + i) * 32;
    unsigned char* dst = g_wt + (size_t)i * 32768;
    const uint32_t rowb = (uint32_t)o * 128;

    #pragma unroll
    for (int half = 0; half < 2; ++half) {
        const float* src = half ? ps : pc;
        #pragma unroll
        for (int g = 0; g < 4; ++g) {
            float4 v0 = *(const float4*)(src + g * 8);
            float4 v1 = *(const float4*)(src + g * 8 + 4);
            uint32_t h[4];
            h[0] = pack_f16(v0.x, v0.y); h[1] = pack_f16(v0.z, v0.w);
            h[2] = pack_f16(v1.x, v1.y); h[3] = pack_f16(v1.z, v1.w);
            uint32_t off = swz(rowb + half * 64 + g * 16);
            *(uint4*)(dst + off) = make_uint4(h[0], h[1], h[2], h[3]);
        }
    }
}

// ---------- main kernel ----------
// SMEM (192KB): stage s (s=0,1):
//   A: SA(s) + d*16384   (d = dim in stage; 128 rows x 128B)    [0,   64K)
//   W: SW(s) + d*32768   (256 rows x 128B)                      [64K, 192K)
#define SA(s)    ((uint32_t)(s) * 32768u)
#define SW(s)    (65536u + (uint32_t)(s) * 65536u)
#define SMEM_SZ  196608

__global__ __launch_bounds__(320, 1)
void kan_mma(const float* __restrict__ x, const float* __restrict__ bias,
             float* __restrict__ out) {
    extern __shared__ __align__(1024) unsigned char sm[];
    const uint32_t sb = smem_u32(sm);
    const int t = threadIdx.x, lane = t & 31, wid = t >> 5;
    const int row0 = blockIdx.x * 128;

    if (wid >= 8) {
        // ========= PRODUCERS (warps 8-9, 64 threads; 2 rows x 2 dims each) =========
        const int pt = t - 256;                    // 0..63
        #pragma unroll 1
        for (int j = 0; j < INDIM / 2; ++j) {      // stage j: dims 2j, 2j+1
            const int s = j & 1;
            if (j >= 2) BAR_SYNC(3 + s);           // consumers freed stage s

            // W: 64KB (two 32KB dim-tiles, contiguous in g_wt) -> SW(s)
            {
                const unsigned char* ws = g_wt + (size_t)(2 * j) * 32768;
                const uint32_t wd = sb + SW(s);
                #pragma unroll 16
                for (int q = 0; q < 64; ++q) {
                    uint32_t off = (uint32_t)pt * 16u + q * 1024u;
                    cpa16(wd + off, ws + off);
                }
                CP_COMMIT();
            }

            // A rows pt and pt+64, dims 2j (d=0) and 2j+1 (d=1)
            #pragma unroll
            for (int rr = 0; rr < 2; ++rr) {
                const int row = pt + rr * 64;
                const float2 xv2 = __ldg((const float2*)(x + (size_t)(row0 + row) * INDIM + 2 * j));
                const uint32_t genrow = (uint32_t)row * 128;
                const uint32_t genxm  = ((uint32_t)row & 7) << 4;
                #pragma unroll
                for (int d = 0; d < 2; ++d) {
                    const float xv = d ? xv2.y : xv2.x;
                    float c1, s1;
                    __sincosf(xv, &s1, &c1);
                    float ck = c1, sk = s1;
                    uint32_t chv[16], shv[16];
                    #pragma unroll
                    for (int p = 0; p < 16; ++p) {
                        float c0 = ck, s0 = sk;
                        float cA = fmaf(ck, c1, -(sk * s1));   // k = 2p+2
                        float sA = fmaf(sk, c1, ck * s1);
                        chv[p] = pack_f16(c0, cA);
                        shv[p] = pack_f16(s0, sA);
                        ck = fmaf(cA, c1, -(sA * s1));         // k = 2p+3
                        sk = fmaf(sA, c1, cA * s1);
                    }
                    const uint32_t ab = sb + SA(s) + (uint32_t)d * 16384u;
                    #pragma unroll
                    for (int g = 0; g < 4; ++g) {
                        uint32_t cb = g * 16;
                        uint32_t oc = genrow + (cb ^ genxm);          // cos cols
                        uint32_t os = genrow + ((cb + 64u) ^ genxm);  // sin cols
                        *(uint4*)(sm + (ab - sb) + oc) = make_uint4(chv[4*g], chv[4*g+1], chv[4*g+2], chv[4*g+3]);
                        *(uint4*)(sm + (ab - sb) + os) = make_uint4(shv[4*g], shv[4*g+1], shv[4*g+2], shv[4*g+3]);
                    }
                }
            }

            CP_WAIT0();                            // W landed (this thread's chunks)
            BAR_ARRIVE(1 + s);                     // publish FULL(s)
        }
        return;
    }

    // ================= CONSUMERS (warps 0-7, 64x64 tiles) =================
    const int wm = wid & 1, wn = wid >> 1;          // 2 x 4 warp grid
    const int m0 = wm * 64, n0 = wn * 64;
    const int a_r   = m0 + (lane & 15);
    const uint32_t a_kadd = (lane & 16) ? 16u : 0u;
    const uint32_t a_xm   = ((uint32_t)a_r & 7) << 4;
    const int b_r   = n0 + (lane & 7) + ((lane & 16) ? 8 : 0);
    const uint32_t b_kadd = (lane & 8) ? 16u : 0u;
    const uint32_t b_xm   = ((uint32_t)b_r & 7) << 4;

    float acc[4][8][4];
    #pragma unroll
    for (int mt = 0; mt < 4; ++mt)
        #pragma unroll
        for (int nt = 0; nt < 8; ++nt)
            #pragma unroll
            for (int e = 0; e < 4; ++e) acc[mt][nt][e] = 0.0f;

    #pragma unroll 1
    for (int j = 0; j < INDIM / 2; ++j) {
        const int s = j & 1;
        BAR_SYNC(1 + s);                            // wait FULL(s)
        #pragma unroll
        for (int ks2 = 0; ks2 < 8; ++ks2) {
            const uint32_t d  = (uint32_t)ks2 >> 2;
            const uint32_t kb = ((uint32_t)ks2 & 3) * 32;
            const uint32_t Ab = sb + SA(s) + d * 16384u;
            const uint32_t Wb = sb + SW(s) + d * 32768u;
            const uint32_t ac = (kb + a_kadd) ^ a_xm;
            const uint32_t bc = (kb + b_kadd) ^ b_xm;
            uint32_t af[4][4];
            #pragma unroll
            for (int mt = 0; mt < 4; ++mt)
                ldsm4(af[mt], Ab + (uint32_t)(a_r + mt * 16) * 128 + ac);
            #pragma unroll
            for (int pr = 0; pr < 4; ++pr) {
                uint32_t bfp[4];
                ldsm4(bfp, Wb + (uint32_t)(b_r + pr * 16) * 128 + bc);
                #pragma unroll
                for (int mt = 0; mt < 4; ++mt)
                    #pragma unroll
                    for (int h = 0; h < 2; ++h)
                        mma_f16(acc[mt][pr * 2 + h], af[mt], bfp[h * 2], bfp[h * 2 + 1]);
            }
        }
        BAR_ARRIVE(3 + s);                          // release EMPTY(s)
    }

    // ---------- epilogue ----------
    const int grp = lane >> 2, tig = lane & 3;
    #pragma unroll
    for (int nt = 0; nt < 8; ++nt) {
        const int cg = n0 + nt * 8 + 2 * tig;
        const float2 bs = *(const float2*)&bias[cg];
        #pragma unroll
        for (int mt = 0; mt < 4; ++mt) {
            const int rg = row0 + m0 + mt * 16 + grp;
            float2 v0 = make_float2(acc[mt][nt][0] + bs.x, acc[mt][nt][1] + bs.y);
            float2 v1 = make_float2(acc[mt][nt][2] + bs.x, acc[mt][nt][3] + bs.y);
            *(float2*)&out[(size_t)rg * OUTDIM + cg]       = v0;
            *(float2*)&out[(size_t)(rg + 8) * OUTDIM + cg] = v1;
        }
    }
}

extern "C" void kernel_launch(void* const* d_in, const int* in_sizes, int n_in,
                              void* d_out, int out_size) {
    const float* x    = (const float*)d_in[0];   // [32768][64]
    const float* w    = (const float*)d_in[1];   // [2][256][64][32]
    const float* bias = (const float*)d_in[2];   // [1][256]
    float* out        = (float*)d_out;           // [32768][256]

    cudaFuncSetAttribute(kan_mma, cudaFuncAttributeMaxDynamicSharedMemorySize, SMEM_SZ);

    kan_wprep<<<64, 256>>>(w);
    kan_mma<<<NROWS / 128, 320, SMEM_SZ>>>(x, bias, out);   // grid (256,1)
}

// round 16
// speedup vs baseline: 1.0600x; 1.0600x over previous
#include <cuda_runtime.h>
#include <cstdint>
#include <math.h>

// NaiveFourierKANLayer, warp-specialized fp16 MMA, 64x64 warp tiles:
//   y[32768,256] = A[32768,4096] @ W[4096,256] + bias
// CTA = 128 rows x 256 outputs, 384 threads:
//   warps 0-7  consumers, (2,4) grid of 64x64 tiles (8 LDSM.x4 per 32 MMAs)
//   warps 8-11 producers (1 row/thread A-gen x 2 dims + 64KB W cp.async)
// Stage = 2 input dims (128 k). 2 stages. SMEM 192KB, 1 CTA/SM.
// (Resubmission of R13 after infra failure — unmeasured, theory untested.)

#define NROWS   32768
#define INDIM   64
#define OUTDIM  256

// ---------- helpers ----------
__device__ __forceinline__ uint32_t smem_u32(const void* p) {
    uint32_t a;
    asm("{ .reg .u64 t; cvta.to.shared.u64 t, %1; cvt.u32.u64 %0, t; }" : "=r"(a) : "l"(p));
    return a;
}
__device__ __forceinline__ uint32_t pack_f16(float e0, float e1) {   // low half = e0
    uint32_t r;
    asm("cvt.rn.f16x2.f32 %0, %1, %2;" : "=r"(r) : "f"(e1), "f"(e0));
    return r;
}
__device__ __forceinline__ uint32_t swz(uint32_t off) { return off ^ ((off >> 3) & 0x70); }

__device__ __forceinline__ void cpa16(uint32_t dst, const void* src) {
    asm volatile("cp.async.cg.shared.global [%0], [%1], 16;" :: "r"(dst), "l"(src) : "memory");
}
#define CP_COMMIT() asm volatile("cp.async.commit_group;" ::: "memory")
#define CP_WAIT0()  asm volatile("cp.async.wait_group 0;" ::: "memory")

// named split barriers, whole-CTA count (384)
#define BAR_SYNC(id)   asm volatile("bar.sync %0, 384;"   :: "r"(id) : "memory")
#define BAR_ARRIVE(id) asm volatile("bar.arrive %0, 384;" :: "r"(id) : "memory")
// FULL[s] = 1+s (producers arrive, consumers sync)
// EMPTY[s] = 3+s (consumers arrive, producers sync)

__device__ __forceinline__ void ldsm4(uint32_t* r, uint32_t addr) {
    asm volatile("ldmatrix.sync.aligned.m8n8.x4.shared.b16 {%0,%1,%2,%3}, [%4];"
                 : "=r"(r[0]), "=r"(r[1]), "=r"(r[2]), "=r"(r[3]) : "r"(addr));
}
__device__ __forceinline__ void mma_f16(float* d, const uint32_t* a, uint32_t b0, uint32_t b1) {
    asm volatile("mma.sync.aligned.m16n8k16.row.col.f32.f16.f16.f32 "
                 "{%0,%1,%2,%3},{%4,%5,%6,%7},{%8,%9},{%0,%1,%2,%3};"
                 : "+f"(d[0]), "+f"(d[1]), "+f"(d[2]), "+f"(d[3])
                 : "r"(a[0]), "r"(a[1]), "r"(a[2]), "r"(a[3]), "r"(b0), "r"(b1));
}

// ---------- pre-swizzled fp16 W tiles ----------
// g_wt[i] = 32KB tile: 256 rows (o) x 128B; byte (o,c) at swz(o*128+c)
// c = f*2, f in [0,64): f<32 -> cos k=f+1 ; f>=32 -> sin k=f-31
__device__ __align__(1024) unsigned char g_wt[64 * 32768];

__global__ void kan_wprep(const float* __restrict__ w) {
    const int i = blockIdx.x;
    const int o = threadIdx.x;           // 0..255
    const float* pc = w + ((size_t)(0 * 256 + o) * 64 + i) * 32;
    const float* ps = w + ((size_t)(1 * 256 + o) * 64 + i) * 32;
    unsigned char* dst = g_wt + (size_t)i * 32768;
    const uint32_t rowb = (uint32_t)o * 128;

    #pragma unroll
    for (int half = 0; half < 2; ++half) {
        const float* src = half ? ps : pc;
        #pragma unroll
        for (int g = 0; g < 4; ++g) {
            float4 v0 = *(const float4*)(src + g * 8);
            float4 v1 = *(const float4*)(src + g * 8 + 4);
            uint32_t h[4];
            h[0] = pack_f16(v0.x, v0.y); h[1] = pack_f16(v0.z, v0.w);
            h[2] = pack_f16(v1.x, v1.y); h[3] = pack_f16(v1.z, v1.w);
            uint32_t off = swz(rowb + half * 64 + g * 16);
            *(uint4*)(dst + off) = make_uint4(h[0], h[1], h[2], h[3]);
        }
    }
}

// ---------- main kernel ----------
// SMEM (192KB): stage s (s=0,1):
//   A: SA(s) + d*16384   (d = dim in stage; 128 rows x 128B)    [0,   64K)
//   W: SW(s) + d*32768   (256 rows x 128B)                      [64K, 192K)
#define SA(s)    ((uint32_t)(s) * 32768u)
#define SW(s)    (65536u + (uint32_t)(s) * 65536u)
#define SMEM_SZ  196608

__global__ __launch_bounds__(384, 1)
void kan_mma(const float* __restrict__ x, const float* __restrict__ bias,
             float* __restrict__ out) {
    extern __shared__ __align__(1024) unsigned char sm[];
    const uint32_t sb = smem_u32(sm);
    const int t = threadIdx.x, lane = t & 31, wid = t >> 5;
    const int row0 = blockIdx.x * 128;

    if (wid >= 8) {
        // ======== PRODUCERS (warps 8-11, 128 threads; 1 row, 2 dims each) ========
        const int ar = t - 256;                    // row 0..127
        const uint32_t genrow = (uint32_t)ar * 128;
        const uint32_t genxm  = ((uint32_t)ar & 7) << 4;
        const float* xrow = x + (size_t)(row0 + ar) * INDIM;

        #pragma unroll 1
        for (int j = 0; j < INDIM / 2; ++j) {      // stage j: dims 2j, 2j+1
            const int s = j & 1;
            if (j >= 2) BAR_SYNC(3 + s);           // consumers freed stage s

            // W: 64KB (two contiguous 32KB dim-tiles) -> SW(s); 32 x 16B/thread
            {
                const unsigned char* ws = g_wt + (size_t)(2 * j) * 32768;
                const uint32_t wd = sb + SW(s);
                #pragma unroll 8
                for (int q = 0; q < 32; ++q) {
                    uint32_t off = (uint32_t)ar * 16u + q * 2048u;
                    cpa16(wd + off, ws + off);
                }
                CP_COMMIT();
            }

            // A row ar, dims 2j (d=0), 2j+1 (d=1)
            const float2 xv2 = __ldg((const float2*)(xrow + 2 * j));
            #pragma unroll
            for (int d = 0; d < 2; ++d) {
                const float xv = d ? xv2.y : xv2.x;
                float c1, s1;
                __sincosf(xv, &s1, &c1);
                float ck = c1, sk = s1;
                uint32_t chv[16], shv[16];
                #pragma unroll
                for (int p = 0; p < 16; ++p) {
                    float c0 = ck, s0 = sk;
                    float cA = fmaf(ck, c1, -(sk * s1));   // k = 2p+2
                    float sA = fmaf(sk, c1, ck * s1);
                    chv[p] = pack_f16(c0, cA);
                    shv[p] = pack_f16(s0, sA);
                    ck = fmaf(cA, c1, -(sA * s1));         // k = 2p+3
                    sk = fmaf(sA, c1, cA * s1);
                }
                const uint32_t ab = SA(s) + (uint32_t)d * 16384u;
                #pragma unroll
                for (int g = 0; g < 4; ++g) {
                    uint32_t cb = g * 16;
                    uint32_t oc = genrow + (cb ^ genxm);          // cos cols
                    uint32_t os = genrow + ((cb + 64u) ^ genxm);  // sin cols
                    *(uint4*)(sm + ab + oc) = make_uint4(chv[4*g], chv[4*g+1], chv[4*g+2], chv[4*g+3]);
                    *(uint4*)(sm + ab + os) = make_uint4(shv[4*g], shv[4*g+1], shv[4*g+2], shv[4*g+3]);
                }
            }

            CP_WAIT0();                            // W landed (this thread's chunks)
            BAR_ARRIVE(1 + s);                     // publish FULL(s)
        }
        return;
    }

    // ================= CONSUMERS (warps 0-7, 64x64 tiles) =================
    const int wm = wid & 1, wn = wid >> 1;          // 2 x 4 warp grid
    const int m0 = wm * 64, n0 = wn * 64;
    const int a_r   = m0 + (lane & 15);
    const uint32_t a_kadd = (lane & 16) ? 16u : 0u;
    const uint32_t a_xm   = ((uint32_t)a_r & 7) << 4;
    const int b_r   = n0 + (lane & 7) + ((lane & 16) ? 8 : 0);
    const uint32_t b_kadd = (lane & 8) ? 16u : 0u;
    const uint32_t b_xm   = ((uint32_t)b_r & 7) << 4;

    // hoisted row bases (bytes)
    uint32_t a_base[4], b_base[4];
    #pragma unroll
    for (int mt = 0; mt < 4; ++mt) a_base[mt] = (uint32_t)(a_r + mt * 16) * 128;
    #pragma unroll
    for (int pr = 0; pr < 4; ++pr) b_base[pr] = (uint32_t)(b_r + pr * 16) * 128;

    float acc[4][8][4];
    #pragma unroll
    for (int mt = 0; mt < 4; ++mt)
        #pragma unroll
        for (int nt = 0; nt < 8; ++nt)
            #pragma unroll
            for (int e = 0; e < 4; ++e) acc[mt][nt][e] = 0.0f;

    #pragma unroll 1
    for (int j = 0; j < INDIM / 2; ++j) {
        const int s = j & 1;
        BAR_SYNC(1 + s);                            // wait FULL(s)
        #pragma unroll
        for (int d = 0; d < 2; ++d) {               // dim within stage
            const uint32_t Ab = sb + SA(s) + (uint32_t)d * 16384u;
            const uint32_t Wb = sb + SW(s) + (uint32_t)d * 32768u;
            #pragma unroll
            for (int ksl = 0; ksl < 4; ++ksl) {     // K chunk within dim
                const uint32_t kb = (uint32_t)ksl * 32;
                const uint32_t ac = (kb + a_kadd) ^ a_xm;
                const uint32_t bc = (kb + b_kadd) ^ b_xm;
                uint32_t af[4][4];
                #pragma unroll
                for (int mt = 0; mt < 4; ++mt)
                    ldsm4(af[mt], Ab + a_base[mt] + ac);
                #pragma unroll
                for (int pr = 0; pr < 4; ++pr) {
                    uint32_t bfp[4];
                    ldsm4(bfp, Wb + b_base[pr] + bc);
                    #pragma unroll
                    for (int mt = 0; mt < 4; ++mt)
                        #pragma unroll
                        for (int h = 0; h < 2; ++h)
                            mma_f16(acc[mt][pr * 2 + h], af[mt], bfp[h * 2], bfp[h * 2 + 1]);
                }
            }
        }
        BAR_ARRIVE(3 + s);                          // release EMPTY(s)
    }

    // ---------- epilogue ----------
    const int grp = lane >> 2, tig = lane & 3;
    #pragma unroll
    for (int nt = 0; nt < 8; ++nt) {
        const int cg = n0 + nt * 8 + 2 * tig;
        const float2 bs = *(const float2*)&bias[cg];
        #pragma unroll
        for (int mt = 0; mt < 4; ++mt) {
            const int rg = row0 + m0 + mt * 16 + grp;
            float2 v0 = make_float2(acc[mt][nt][0] + bs.x, acc[mt][nt][1] + bs.y);
            float2 v1 = make_float2(acc[mt][nt][2] + bs.x, acc[mt][nt][3] + bs.y);
            *(float2*)&out[(size_t)rg * OUTDIM + cg]       = v0;
            *(float2*)&out[(size_t)(rg + 8) * OUTDIM + cg] = v1;
        }
    }
}

extern "C" void kernel_launch(void* const* d_in, const int* in_sizes, int n_in,
                              void* d_out, int out_size) {
    const float* x    = (const float*)d_in[0];   // [32768][64]
    const float* w    = (const float*)d_in[1];   // [2][256][64][32]
    const float* bias = (const float*)d_in[2];   // [1][256]
    float* out        = (float*)d_out;           // [32768][256]

    cudaFuncSetAttribute(kan_mma, cudaFuncAttributeMaxDynamicSharedMemorySize, SMEM_SZ);

    kan_wprep<<<64, 256>>>(w);
    kan_mma<<<NROWS / 128, 384, SMEM_SZ>>>(x, bias, out);   // grid (256,1)
}